// round 2
// baseline (speedup 1.0000x reference)
#include <cuda_runtime.h>
#include <math.h>

#define NUM_TOKENS 8192
#define HIDDEN     4096
#define NEXP       512
#define TOPK       12
#define RSCALE     2.5f

// 16 MB scratch for logits (device global: allocation-free per harness rules)
__device__ float g_logits[(size_t)NUM_TOKENS * NEXP];

// ---------------------------------------------------------------------------
// packed-f32x2 helpers (2 fp32 FMAs per instruction; per-lane IEEE FMA)
// ---------------------------------------------------------------------------
__device__ __forceinline__ unsigned long long pack_dup(float x) {
    unsigned long long r;
    unsigned u = __float_as_uint(x);
    asm("mov.b64 %0, {%1, %2};" : "=l"(r) : "r"(u), "r"(u));
    return r;
}
__device__ __forceinline__ void fma2(unsigned long long& d,
                                     unsigned long long a,
                                     unsigned long long b) {
    asm("fma.rn.f32x2 %0, %1, %2, %0;" : "+l"(d) : "l"(a), "l"(b));
}
__device__ __forceinline__ void unpack2(unsigned long long p, float& lo, float& hi) {
    unsigned ulo, uhi;
    asm("mov.b64 {%0, %1}, %2;" : "=r"(ulo), "=r"(uhi) : "l"(p));
    lo = __uint_as_float(ulo);
    hi = __uint_as_float(uhi);
}

// ---------------------------------------------------------------------------
// Kernel 1: logits[t,e] = dot(A[t,:], B[e,:])   (A=[T,H], B=[E,H], K-major)
// Block tile 128x64, BK=8, 256 threads, 8x4 per-thread outputs.
// Accuracy: 32-term fp32 chunks rolled into fp64 accumulators (error ~2.5e-7)
// so top-k selections match the (exact-fp32-level) reference.
// ---------------------------------------------------------------------------
__global__ void __launch_bounds__(256) gemm_logits(const float* __restrict__ A,
                                                   const float* __restrict__ B) {
    __shared__ float As[8][128];
    __shared__ float Bs[8][64];

    const int tid = threadIdx.x;
    const int m0  = blockIdx.y * 128;
    const int n0  = blockIdx.x * 64;
    const int tx  = tid & 15;   // 16 col-groups of 4  -> 64 cols
    const int ty  = tid >> 4;   // 16 row-groups of 8  -> 128 rows (split 0/64)

    // loaders: A uses all 256 threads (128 rows x 2 float4/k-slab),
    //          B uses first 128 threads (64 rows x 2 float4/k-slab)
    const int lrow = tid >> 1;          // 0..127 (A) / 0..63 (B, tid<128)
    const int lk   = (tid & 1) * 4;     // 0 or 4
    const float* Ap = A + (size_t)(m0 + lrow) * HIDDEN + lk;
    const float* Bp = B + (size_t)(n0 + (lrow & 63)) * HIDDEN + lk;

    // fp64 accumulators: 8 rows x 4 cols
    double dacc[8][4];
#pragma unroll
    for (int i = 0; i < 8; i++)
#pragma unroll
        for (int j = 0; j < 4; j++) dacc[i][j] = 0.0;

    // fp32x2 chunk accumulators: 8 rows x 2 col-pairs
    unsigned long long chunk[8][2];
#pragma unroll
    for (int i = 0; i < 8; i++) { chunk[i][0] = 0ull; chunk[i][1] = 0ull; }

    float4 pa = *(const float4*)(Ap);
    float4 pb = make_float4(0.f, 0.f, 0.f, 0.f);
    if (tid < 128) pb = *(const float4*)(Bp);

    for (int k0 = 0; k0 < HIDDEN; k0 += 8) {
        __syncthreads();
        As[lk + 0][lrow] = pa.x; As[lk + 1][lrow] = pa.y;
        As[lk + 2][lrow] = pa.z; As[lk + 3][lrow] = pa.w;
        if (tid < 128) {
            Bs[lk + 0][lrow] = pb.x; Bs[lk + 1][lrow] = pb.y;
            Bs[lk + 2][lrow] = pb.z; Bs[lk + 3][lrow] = pb.w;
        }
        __syncthreads();

        if (k0 + 8 < HIDDEN) {   // prefetch next slab into registers
            pa = *(const float4*)(Ap + k0 + 8);
            if (tid < 128) pb = *(const float4*)(Bp + k0 + 8);
        }

#pragma unroll
        for (int k = 0; k < 8; k++) {
            float4 aA = *(const float4*)&As[k][ty * 4];
            float4 aB = *(const float4*)&As[k][64 + ty * 4];
            ulonglong2 bb = *(const ulonglong2*)&Bs[k][tx * 4];  // cols (c0,c1),(c2,c3)

            unsigned long long ad[8];
            ad[0] = pack_dup(aA.x); ad[1] = pack_dup(aA.y);
            ad[2] = pack_dup(aA.z); ad[3] = pack_dup(aA.w);
            ad[4] = pack_dup(aB.x); ad[5] = pack_dup(aB.y);
            ad[6] = pack_dup(aB.z); ad[7] = pack_dup(aB.w);

#pragma unroll
            for (int i = 0; i < 8; i++) {
                fma2(chunk[i][0], ad[i], bb.x);
                fma2(chunk[i][1], ad[i], bb.y);
            }
        }

        // every 4 BK-slabs (32 k-terms): roll fp32 chunks into fp64, reset
        if ((k0 & 24) == 24) {
#pragma unroll
            for (int i = 0; i < 8; i++) {
#pragma unroll
                for (int jp = 0; jp < 2; jp++) {
                    float lo, hi;
                    unpack2(chunk[i][jp], lo, hi);
                    dacc[i][2 * jp + 0] += (double)lo;
                    dacc[i][2 * jp + 1] += (double)hi;
                    chunk[i][jp] = 0ull;
                }
            }
        }
    }

    // writeback: 4 consecutive cols per row -> float4 stores
#pragma unroll
    for (int i = 0; i < 8; i++) {
        int row = m0 + ((i < 4) ? (ty * 4 + i) : (64 + ty * 4 + (i - 4)));
        float4 v;
        v.x = (float)dacc[i][0]; v.y = (float)dacc[i][1];
        v.z = (float)dacc[i][2]; v.w = (float)dacc[i][3];
        *(float4*)&g_logits[(size_t)row * NEXP + n0 + tx * 4] = v;
    }
}

// ---------------------------------------------------------------------------
// Kernel 2: softmax over 512 experts, biased top-12 (ties -> lowest index,
// matching jax.lax.top_k), gather unbiased probs * 2.5.
// One block per token, 512 threads (1 expert/thread).
// out layout: [weights (T*K floats)] then [expert indices as floats (T*K)]
// ---------------------------------------------------------------------------
__global__ void __launch_bounds__(512) softmax_topk(const float* __restrict__ bias,
                                                    float* __restrict__ out) {
    const int t    = blockIdx.x;
    const int e    = threadIdx.x;
    const int lane = e & 31;
    const int warp = e >> 5;  // 0..15

    __shared__ float s_v[16];
    __shared__ int   s_i[16];
    __shared__ float s_bcast;
    __shared__ int   s_sel;

    float logit = g_logits[(size_t)t * NEXP + e];

    // ---- block max ----
    float m = logit;
#pragma unroll
    for (int off = 16; off; off >>= 1)
        m = fmaxf(m, __shfl_xor_sync(0xffffffffu, m, off));
    if (lane == 0) s_v[warp] = m;
    __syncthreads();
    if (warp == 0) {
        float v = (lane < 16) ? s_v[lane] : -INFINITY;
#pragma unroll
        for (int off = 16; off; off >>= 1)
            v = fmaxf(v, __shfl_xor_sync(0xffffffffu, v, off));
        if (lane == 0) s_bcast = v;
    }
    __syncthreads();
    const float mx = s_bcast;
    const float p  = expf(logit - mx);

    // ---- block sum ----
    float s = p;
#pragma unroll
    for (int off = 16; off; off >>= 1)
        s += __shfl_xor_sync(0xffffffffu, s, off);
    if (lane == 0) s_v[warp] = s;
    __syncthreads();
    if (warp == 0) {
        float v = (lane < 16) ? s_v[lane] : 0.0f;
#pragma unroll
        for (int off = 16; off; off >>= 1)
            v += __shfl_xor_sync(0xffffffffu, v, off);
        if (lane == 0) s_bcast = v;
    }
    __syncthreads();
    const float prob = p / s_bcast;

    float biased = prob + bias[e];

    // ---- sequential top-12 argmax (descending; ties -> smallest index) ----
    for (int it = 0; it < TOPK; it++) {
        float v = biased;
        int   idx = e;
#pragma unroll
        for (int off = 16; off; off >>= 1) {
            float ov = __shfl_xor_sync(0xffffffffu, v, off);
            int   oi = __shfl_xor_sync(0xffffffffu, idx, off);
            if (ov > v || (ov == v && oi < idx)) { v = ov; idx = oi; }
        }
        if (lane == 0) { s_v[warp] = v; s_i[warp] = idx; }
        __syncthreads();
        if (warp == 0) {
            float v2 = (lane < 16) ? s_v[lane] : -INFINITY;
            int   i2 = (lane < 16) ? s_i[lane] : 0x7fffffff;
#pragma unroll
            for (int off = 16; off; off >>= 1) {
                float ov = __shfl_xor_sync(0xffffffffu, v2, off);
                int   oi = __shfl_xor_sync(0xffffffffu, i2, off);
                if (ov > v2 || (ov == v2 && oi < i2)) { v2 = ov; i2 = oi; }
            }
            if (lane == 0) s_sel = i2;
        }
        __syncthreads();
        const int sel = s_sel;
        if (e == sel) {
            out[(size_t)t * TOPK + it]                             = prob * RSCALE;
            out[(size_t)NUM_TOKENS * TOPK + (size_t)t * TOPK + it] = (float)sel;
            biased = -INFINITY;  // mask for subsequent iterations
        }
    }
}

// ---------------------------------------------------------------------------
extern "C" void kernel_launch(void* const* d_in, const int* in_sizes, int n_in,
                              void* d_out, int out_size) {
    const float* hs   = (const float*)d_in[0];  // hidden_states [8192,4096]
    const float* w    = (const float*)d_in[1];  // classifier_weight [512,4096]
    const float* bias = (const float*)d_in[2];  // e_score_correction_bias [512]
    float* out = (float*)d_out;

    dim3 grid(NEXP / 64, NUM_TOKENS / 128);     // (8, 64)
    gemm_logits<<<grid, 256>>>(hs, w);
    softmax_topk<<<NUM_TOKENS, 512>>>(bias, out);
}

// round 3
// speedup vs baseline: 1.0003x; 1.0003x over previous
#include <cuda_runtime.h>
#include <math.h>

#define NUM_TOKENS 8192
#define HIDDEN     4096
#define NEXP       512
#define TOPK       12
#define RSCALE     2.5f

// 16 MB scratch for logits (device global: allocation-free per harness rules)
__device__ float g_logits[(size_t)NUM_TOKENS * NEXP];

// ---------------------------------------------------------------------------
// packed-f32x2 helpers (2 fp32 FMAs per instruction; per-lane IEEE FMA)
// ---------------------------------------------------------------------------
__device__ __forceinline__ unsigned long long pack_dup(float x) {
    unsigned long long r;
    unsigned u = __float_as_uint(x);
    asm("mov.b64 %0, {%1, %2};" : "=l"(r) : "r"(u), "r"(u));
    return r;
}
__device__ __forceinline__ void fma2(unsigned long long& d,
                                     unsigned long long a,
                                     unsigned long long b) {
    asm("fma.rn.f32x2 %0, %1, %2, %0;" : "+l"(d) : "l"(a), "l"(b));
}
__device__ __forceinline__ void unpack2(unsigned long long p, float& lo, float& hi) {
    unsigned ulo, uhi;
    asm("mov.b64 {%0, %1}, %2;" : "=r"(ulo), "=r"(uhi) : "l"(p));
    lo = __uint_as_float(ulo);
    hi = __uint_as_float(uhi);
}

// ---------------------------------------------------------------------------
// Kernel 1: logits[t,e] = dot(A[t,:], B[e,:])   (A=[T,H], B=[E,H], K-major)
// Block tile 128x64, BK=8, 256 threads, 8x4 per-thread outputs.
// Accuracy: 32-term fp32 chunks rolled into fp64 accumulators (error ~2.5e-7)
// so top-k selections match the (exact-fp32-level) reference.
// ---------------------------------------------------------------------------
__global__ void __launch_bounds__(256) gemm_logits(const float* __restrict__ A,
                                                   const float* __restrict__ B) {
    __shared__ float As[8][128];
    __shared__ float Bs[8][64];

    const int tid = threadIdx.x;
    const int m0  = blockIdx.y * 128;
    const int n0  = blockIdx.x * 64;
    const int tx  = tid & 15;   // 16 col-groups of 4  -> 64 cols
    const int ty  = tid >> 4;   // 16 row-groups of 8  -> 128 rows (split 0/64)

    // loaders: A uses all 256 threads (128 rows x 2 float4/k-slab),
    //          B uses first 128 threads (64 rows x 2 float4/k-slab)
    const int lrow = tid >> 1;          // 0..127 (A) / 0..63 (B, tid<128)
    const int lk   = (tid & 1) * 4;     // 0 or 4
    const float* Ap = A + (size_t)(m0 + lrow) * HIDDEN + lk;
    const float* Bp = B + (size_t)(n0 + (lrow & 63)) * HIDDEN + lk;

    // fp64 accumulators: 8 rows x 4 cols
    double dacc[8][4];
#pragma unroll
    for (int i = 0; i < 8; i++)
#pragma unroll
        for (int j = 0; j < 4; j++) dacc[i][j] = 0.0;

    // fp32x2 chunk accumulators: 8 rows x 2 col-pairs
    unsigned long long chunk[8][2];
#pragma unroll
    for (int i = 0; i < 8; i++) { chunk[i][0] = 0ull; chunk[i][1] = 0ull; }

    float4 pa = *(const float4*)(Ap);
    float4 pb = make_float4(0.f, 0.f, 0.f, 0.f);
    if (tid < 128) pb = *(const float4*)(Bp);

    for (int k0 = 0; k0 < HIDDEN; k0 += 8) {
        __syncthreads();
        As[lk + 0][lrow] = pa.x; As[lk + 1][lrow] = pa.y;
        As[lk + 2][lrow] = pa.z; As[lk + 3][lrow] = pa.w;
        if (tid < 128) {
            Bs[lk + 0][lrow] = pb.x; Bs[lk + 1][lrow] = pb.y;
            Bs[lk + 2][lrow] = pb.z; Bs[lk + 3][lrow] = pb.w;
        }
        __syncthreads();

        if (k0 + 8 < HIDDEN) {   // prefetch next slab into registers
            pa = *(const float4*)(Ap + k0 + 8);
            if (tid < 128) pb = *(const float4*)(Bp + k0 + 8);
        }

#pragma unroll
        for (int k = 0; k < 8; k++) {
            float4 aA = *(const float4*)&As[k][ty * 4];
            float4 aB = *(const float4*)&As[k][64 + ty * 4];
            ulonglong2 bb = *(const ulonglong2*)&Bs[k][tx * 4];  // cols (c0,c1),(c2,c3)

            unsigned long long ad[8];
            ad[0] = pack_dup(aA.x); ad[1] = pack_dup(aA.y);
            ad[2] = pack_dup(aA.z); ad[3] = pack_dup(aA.w);
            ad[4] = pack_dup(aB.x); ad[5] = pack_dup(aB.y);
            ad[6] = pack_dup(aB.z); ad[7] = pack_dup(aB.w);

#pragma unroll
            for (int i = 0; i < 8; i++) {
                fma2(chunk[i][0], ad[i], bb.x);
                fma2(chunk[i][1], ad[i], bb.y);
            }
        }

        // every 4 BK-slabs (32 k-terms): roll fp32 chunks into fp64, reset
        if ((k0 & 24) == 24) {
#pragma unroll
            for (int i = 0; i < 8; i++) {
#pragma unroll
                for (int jp = 0; jp < 2; jp++) {
                    float lo, hi;
                    unpack2(chunk[i][jp], lo, hi);
                    dacc[i][2 * jp + 0] += (double)lo;
                    dacc[i][2 * jp + 1] += (double)hi;
                    chunk[i][jp] = 0ull;
                }
            }
        }
    }

    // writeback: 4 consecutive cols per row -> float4 stores
#pragma unroll
    for (int i = 0; i < 8; i++) {
        int row = m0 + ((i < 4) ? (ty * 4 + i) : (64 + ty * 4 + (i - 4)));
        float4 v;
        v.x = (float)dacc[i][0]; v.y = (float)dacc[i][1];
        v.z = (float)dacc[i][2]; v.w = (float)dacc[i][3];
        *(float4*)&g_logits[(size_t)row * NEXP + n0 + tx * 4] = v;
    }
}

// ---------------------------------------------------------------------------
// Kernel 2: softmax over 512 experts, biased top-12 (ties -> lowest index,
// matching jax.lax.top_k), gather unbiased probs * 2.5.
// One block per token, 512 threads (1 expert/thread).
// out layout: [weights (T*K floats)] then [expert indices as floats (T*K)]
// ---------------------------------------------------------------------------
__global__ void __launch_bounds__(512) softmax_topk(const float* __restrict__ bias,
                                                    float* __restrict__ out) {
    const int t    = blockIdx.x;
    const int e    = threadIdx.x;
    const int lane = e & 31;
    const int warp = e >> 5;  // 0..15

    __shared__ float s_v[16];
    __shared__ int   s_i[16];
    __shared__ float s_bcast;
    __shared__ int   s_sel;

    float logit = g_logits[(size_t)t * NEXP + e];

    // ---- block max ----
    float m = logit;
#pragma unroll
    for (int off = 16; off; off >>= 1)
        m = fmaxf(m, __shfl_xor_sync(0xffffffffu, m, off));
    if (lane == 0) s_v[warp] = m;
    __syncthreads();
    if (warp == 0) {
        float v = (lane < 16) ? s_v[lane] : -INFINITY;
#pragma unroll
        for (int off = 16; off; off >>= 1)
            v = fmaxf(v, __shfl_xor_sync(0xffffffffu, v, off));
        if (lane == 0) s_bcast = v;
    }
    __syncthreads();
    const float mx = s_bcast;
    const float p  = expf(logit - mx);

    // ---- block sum ----
    float s = p;
#pragma unroll
    for (int off = 16; off; off >>= 1)
        s += __shfl_xor_sync(0xffffffffu, s, off);
    if (lane == 0) s_v[warp] = s;
    __syncthreads();
    if (warp == 0) {
        float v = (lane < 16) ? s_v[lane] : 0.0f;
#pragma unroll
        for (int off = 16; off; off >>= 1)
            v += __shfl_xor_sync(0xffffffffu, v, off);
        if (lane == 0) s_bcast = v;
    }
    __syncthreads();
    const float prob = p / s_bcast;

    float biased = prob + bias[e];

    // ---- sequential top-12 argmax (descending; ties -> smallest index) ----
    for (int it = 0; it < TOPK; it++) {
        float v = biased;
        int   idx = e;
#pragma unroll
        for (int off = 16; off; off >>= 1) {
            float ov = __shfl_xor_sync(0xffffffffu, v, off);
            int   oi = __shfl_xor_sync(0xffffffffu, idx, off);
            if (ov > v || (ov == v && oi < idx)) { v = ov; idx = oi; }
        }
        if (lane == 0) { s_v[warp] = v; s_i[warp] = idx; }
        __syncthreads();
        if (warp == 0) {
            float v2 = (lane < 16) ? s_v[lane] : -INFINITY;
            int   i2 = (lane < 16) ? s_i[lane] : 0x7fffffff;
#pragma unroll
            for (int off = 16; off; off >>= 1) {
                float ov = __shfl_xor_sync(0xffffffffu, v2, off);
                int   oi = __shfl_xor_sync(0xffffffffu, i2, off);
                if (ov > v2 || (ov == v2 && oi < i2)) { v2 = ov; i2 = oi; }
            }
            if (lane == 0) s_sel = i2;
        }
        __syncthreads();
        const int sel = s_sel;
        if (e == sel) {
            out[(size_t)t * TOPK + it]                             = prob * RSCALE;
            out[(size_t)NUM_TOKENS * TOPK + (size_t)t * TOPK + it] = (float)sel;
            biased = -INFINITY;  // mask for subsequent iterations
        }
    }
}

// ---------------------------------------------------------------------------
extern "C" void kernel_launch(void* const* d_in, const int* in_sizes, int n_in,
                              void* d_out, int out_size) {
    const float* hs   = (const float*)d_in[0];  // hidden_states [8192,4096]
    const float* w    = (const float*)d_in[1];  // classifier_weight [512,4096]
    const float* bias = (const float*)d_in[2];  // e_score_correction_bias [512]
    float* out = (float*)d_out;

    dim3 grid(NEXP / 64, NUM_TOKENS / 128);     // (8, 64)
    gemm_logits<<<grid, 256>>>(hs, w);
    softmax_topk<<<NUM_TOKENS, 512>>>(bias, out);
}

// round 9
// speedup vs baseline: 4.8914x; 4.8900x over previous
#include <cuda_runtime.h>
#include <cuda_bf16.h>
#include <math.h>
#include <stdint.h>

#define NUM_TOKENS 8192
#define HIDDEN     4096
#define NEXP       512
#define TOPK       12
#define RSCALE     2.5f

#define TILE_M 128
#define TILE_N 64
#define BK     64
#define NCHUNK (HIDDEN / BK)      // 64

// device-global scratch (allocation-free per harness rules)
__device__ float g_logits[(size_t)NUM_TOKENS * NEXP];
__device__ __nv_bfloat16 gA0[(size_t)NUM_TOKENS * HIDDEN];
__device__ __nv_bfloat16 gA1[(size_t)NUM_TOKENS * HIDDEN];
__device__ __nv_bfloat16 gA2[(size_t)NUM_TOKENS * HIDDEN];
__device__ __nv_bfloat16 gB0[(size_t)NEXP * HIDDEN];
__device__ __nv_bfloat16 gB1[(size_t)NEXP * HIDDEN];
__device__ __nv_bfloat16 gB2[(size_t)NEXP * HIDDEN];

// ---------------------------------------------------------------------------
// helpers (base-ISA only: ldmatrix + mma.sync + cp.async; NO tcgen05)
// ---------------------------------------------------------------------------
__device__ __forceinline__ uint32_t smem_u32(const void* p) {
    uint32_t a;
    asm("{ .reg .u64 t; cvta.to.shared.u64 t, %1; cvt.u32.u64 %0, t; }" : "=r"(a) : "l"(p));
    return a;
}
#define SWZ(off) ((off) ^ (((off) >> 3) & 0x70))

__device__ __forceinline__ void cp16(uint32_t dst, const void* src) {
    asm volatile("cp.async.cg.shared.global [%0], [%1], 16;" :: "r"(dst), "l"(src) : "memory");
}
__device__ __forceinline__ void ldsm4(uint32_t* r, uint32_t addr) {
    asm volatile("ldmatrix.sync.aligned.m8n8.x4.shared.b16 {%0,%1,%2,%3}, [%4];"
                 : "=r"(r[0]), "=r"(r[1]), "=r"(r[2]), "=r"(r[3]) : "r"(addr));
}
__device__ __forceinline__ void mma_bf16(float* c, const uint32_t* a, const uint32_t* b) {
    asm volatile(
        "mma.sync.aligned.m16n8k16.row.col.f32.bf16.bf16.f32 "
        "{%0,%1,%2,%3}, {%4,%5,%6,%7}, {%8,%9}, {%0,%1,%2,%3};"
        : "+f"(c[0]), "+f"(c[1]), "+f"(c[2]), "+f"(c[3])
        : "r"(a[0]), "r"(a[1]), "r"(a[2]), "r"(a[3]), "r"(b[0]), "r"(b[1]));
}

// ---------------------------------------------------------------------------
// Kernel 0: 3-way bf16 split of fp32 tensor (a = a0 + a1 + a2)
// ---------------------------------------------------------------------------
__device__ __forceinline__ void split1(float x, uint16_t& b0, uint16_t& b1, uint16_t& b2) {
    __nv_bfloat16 h0 = __float2bfloat16_rn(x);
    float r = x - __bfloat162float(h0);
    __nv_bfloat16 h1 = __float2bfloat16_rn(r);
    float r2 = r - __bfloat162float(h1);
    __nv_bfloat16 h2 = __float2bfloat16_rn(r2);
    b0 = __bfloat16_as_ushort(h0);
    b1 = __bfloat16_as_ushort(h1);
    b2 = __bfloat16_as_ushort(h2);
}
__global__ void split3_kernel(const float* __restrict__ src, int n4, int which) {
    __nv_bfloat16 *d0 = which ? gB0 : gA0;
    __nv_bfloat16 *d1 = which ? gB1 : gA1;
    __nv_bfloat16 *d2 = which ? gB2 : gA2;
    for (int i = blockIdx.x * blockDim.x + threadIdx.x; i < n4; i += gridDim.x * blockDim.x) {
        float4 v = ((const float4*)src)[i];
        uint16_t a0[4], a1[4], a2[4];
        split1(v.x, a0[0], a1[0], a2[0]);
        split1(v.y, a0[1], a1[1], a2[1]);
        split1(v.z, a0[2], a1[2], a2[2]);
        split1(v.w, a0[3], a1[3], a2[3]);
        uint2 p0 = make_uint2((uint32_t)a0[0] | ((uint32_t)a0[1] << 16),
                              (uint32_t)a0[2] | ((uint32_t)a0[3] << 16));
        uint2 p1 = make_uint2((uint32_t)a1[0] | ((uint32_t)a1[1] << 16),
                              (uint32_t)a1[2] | ((uint32_t)a1[3] << 16));
        uint2 p2 = make_uint2((uint32_t)a2[0] | ((uint32_t)a2[1] << 16),
                              (uint32_t)a2[2] | ((uint32_t)a2[3] << 16));
        ((uint2*)d0)[i] = p0;
        ((uint2*)d1)[i] = p1;
        ((uint2*)d2)[i] = p2;
    }
}

// ---------------------------------------------------------------------------
// Kernel 1: HMMA emulated-fp32 GEMM  (logits = A @ B^T)
// SMEM stage (72 KB): A0|A1|A2 (16 KB, 128 rows x 128 B SW128),
//                     B0|B1|B2 ( 8 KB,  64 rows x 128 B SW128)
// ---------------------------------------------------------------------------
#define STAGE_BYTES 73728
#define SMEM_DYN    (2 * STAGE_BYTES)

__device__ __forceinline__ void load_chunk(uint32_t sbase, int s, int c, int m0, int n0, int tid) {
    const int k0 = c * BK;
    const uint32_t st = sbase + s * STAGE_BYTES;
#pragma unroll
    for (int i = 0; i < 12; i++) {          // A: 3 splits x 128 rows x 8 segs
        int o = tid + 256 * i;
        int split = o >> 10;
        int rem = o & 1023;
        int row = rem >> 3, seg = rem & 7;
        const __nv_bfloat16* src = (split == 0) ? gA0 : (split == 1) ? gA1 : gA2;
        const __nv_bfloat16* g = src + (size_t)(m0 + row) * HIDDEN + k0 + seg * 8;
        uint32_t off = row * 128 + seg * 16;
        cp16(st + split * 16384 + SWZ(off), g);
    }
#pragma unroll
    for (int i = 0; i < 6; i++) {           // B: 3 splits x 64 rows x 8 segs
        int o = tid + 256 * i;
        int split = o >> 9;
        int rem = o & 511;
        int row = rem >> 3, seg = rem & 7;
        const __nv_bfloat16* src = (split == 0) ? gB0 : (split == 1) ? gB1 : gB2;
        const __nv_bfloat16* g = src + (size_t)(n0 + row) * HIDDEN + k0 + seg * 8;
        uint32_t off = row * 128 + seg * 16;
        cp16(st + 49152 + split * 8192 + SWZ(off), g);
    }
    asm volatile("cp.async.commit_group;" ::: "memory");
}

__global__ void __launch_bounds__(256, 1) gemm_tc() {
    extern __shared__ char dsm[];
    const uint32_t sbase = smem_u32(dsm);
    const int tid  = threadIdx.x;
    const int wid  = tid >> 5;
    const int lane = tid & 31;
    const int m0 = blockIdx.y * TILE_M;
    const int n0 = blockIdx.x * TILE_N;
    const int wm = (wid >> 1) * 32;     // warp m-offset in tile (4 rows of warps)
    const int wn = (wid & 1) * 32;      // warp n-offset (2 cols of warps)

    // accumulators: [mt(2)][nt(4)][4]
    float accM[32], accS[32], carry[32];
#pragma unroll
    for (int i = 0; i < 32; i++) { accM[i] = 0.f; accS[i] = 0.f; carry[i] = 0.f; }

    // ldmatrix lane-address components (byte offsets inside a 128B-row matrix)
    const int arow = wm + (lane & 15);              // + mt*16
    const int aseg16 = (lane >> 4) * 16;            // k 16B-segment select
    const int brow = wn + ((lane >> 4) << 3) + (lane & 7);   // + half*16
    const int bseg16 = ((lane >> 3) & 1) * 16;

    load_chunk(sbase, 0, 0, m0, n0, tid);
    load_chunk(sbase, 1, 1, m0, n0, tid);
    asm volatile("cp.async.wait_group 1;" ::: "memory");
    __syncthreads();

    for (int c = 0; c < NCHUNK; c++) {
        const int b = c & 1;
        const uint32_t st = sbase + b * STAGE_BYTES;

#pragma unroll
        for (int ks = 0; ks < 4; ks++) {
            uint32_t a0f[2][4], a1f[2][4], a2f[2][4];
            uint32_t b0f[2][4], b1f[2][4], b2f[2][4];
#pragma unroll
            for (int mt = 0; mt < 2; mt++) {
                int row = arow + mt * 16;
                uint32_t ad = st + row * 128 + ((ks * 32 + aseg16) ^ ((row & 7) << 4));
                ldsm4(a0f[mt], ad);
                ldsm4(a1f[mt], ad + 16384);
                ldsm4(a2f[mt], ad + 32768);
            }
#pragma unroll
            for (int h = 0; h < 2; h++) {
                int row = brow + h * 16;
                uint32_t bd = st + 49152 + row * 128 + ((ks * 32 + bseg16) ^ ((row & 7) << 4));
                ldsm4(b0f[h], bd);
                ldsm4(b1f[h], bd + 8192);
                ldsm4(b2f[h], bd + 16384);
            }
#pragma unroll
            for (int mt = 0; mt < 2; mt++) {
#pragma unroll
                for (int nt = 0; nt < 4; nt++) {
                    float* cM = accM + (mt * 4 + nt) * 4;
                    float* cS = accS + (mt * 4 + nt) * 4;
                    const uint32_t* B0 = &b0f[nt >> 1][(nt & 1) * 2];
                    const uint32_t* B1 = &b1f[nt >> 1][(nt & 1) * 2];
                    const uint32_t* B2 = &b2f[nt >> 1][(nt & 1) * 2];
                    mma_bf16(cM, a0f[mt], B0);      // main hi*hi
                    mma_bf16(cS, a0f[mt], B1);      // 2^-9 cross terms
                    mma_bf16(cS, a1f[mt], B0);
                    mma_bf16(cS, a0f[mt], B2);      // 2^-18 terms
                    mma_bf16(cS, a1f[mt], B1);
                    mma_bf16(cS, a2f[mt], B0);
                }
            }
        }

        // split-K style flush: every 4 chunks roll main accum into carry
        if ((c & 3) == 3) {
#pragma unroll
            for (int i = 0; i < 32; i++) { carry[i] += accM[i]; accM[i] = 0.f; }
        }

        if (c + 2 < NCHUNK) {
            __syncthreads();                               // done reading stage b
            load_chunk(sbase, b, c + 2, m0, n0, tid);
            asm volatile("cp.async.wait_group 1;" ::: "memory");  // chunk c+1 resident
            __syncthreads();
        } else if (c + 1 < NCHUNK) {
            asm volatile("cp.async.wait_group 0;" ::: "memory");
            __syncthreads();
        }
    }

    // writeback: logit = carry(main) + accS(small streams)
#pragma unroll
    for (int mt = 0; mt < 2; mt++) {
#pragma unroll
        for (int nt = 0; nt < 4; nt++) {
            const float* cM = carry + (mt * 4 + nt) * 4;
            const float* cS = accS + (mt * 4 + nt) * 4;
            int r0  = m0 + wm + mt * 16 + (lane >> 2);
            int col = n0 + wn + nt * 8 + (lane & 3) * 2;
            float2 v0 = make_float2(cM[0] + cS[0], cM[1] + cS[1]);
            float2 v1 = make_float2(cM[2] + cS[2], cM[3] + cS[3]);
            *(float2*)&g_logits[(size_t)r0 * NEXP + col]       = v0;
            *(float2*)&g_logits[(size_t)(r0 + 8) * NEXP + col] = v1;
        }
    }
}

// ---------------------------------------------------------------------------
// Kernel 2: softmax over 512 experts, biased top-12 (ties -> lowest index),
// gather unbiased probs * 2.5.  One block per token, 512 threads.
// out layout: [weights (T*K floats)] then [expert indices as floats (T*K)]
// ---------------------------------------------------------------------------
__global__ void __launch_bounds__(512) softmax_topk(const float* __restrict__ bias,
                                                    float* __restrict__ out) {
    const int t    = blockIdx.x;
    const int e    = threadIdx.x;
    const int lane = e & 31;
    const int warp = e >> 5;

    __shared__ float s_v[16];
    __shared__ int   s_i[16];
    __shared__ float s_bcast;
    __shared__ int   s_sel;

    float logit = g_logits[(size_t)t * NEXP + e];

    float m = logit;
#pragma unroll
    for (int off = 16; off; off >>= 1)
        m = fmaxf(m, __shfl_xor_sync(0xffffffffu, m, off));
    if (lane == 0) s_v[warp] = m;
    __syncthreads();
    if (warp == 0) {
        float v = (lane < 16) ? s_v[lane] : -INFINITY;
#pragma unroll
        for (int off = 16; off; off >>= 1)
            v = fmaxf(v, __shfl_xor_sync(0xffffffffu, v, off));
        if (lane == 0) s_bcast = v;
    }
    __syncthreads();
    const float mx = s_bcast;
    const float p  = expf(logit - mx);

    float s = p;
#pragma unroll
    for (int off = 16; off; off >>= 1)
        s += __shfl_xor_sync(0xffffffffu, s, off);
    if (lane == 0) s_v[warp] = s;
    __syncthreads();
    if (warp == 0) {
        float v = (lane < 16) ? s_v[lane] : 0.0f;
#pragma unroll
        for (int off = 16; off; off >>= 1)
            v += __shfl_xor_sync(0xffffffffu, v, off);
        if (lane == 0) s_bcast = v;
    }
    __syncthreads();
    const float prob = p / s_bcast;

    float biased = prob + bias[e];

    for (int it = 0; it < TOPK; it++) {
        float v = biased;
        int   idx = e;
#pragma unroll
        for (int off = 16; off; off >>= 1) {
            float ov = __shfl_xor_sync(0xffffffffu, v, off);
            int   oi = __shfl_xor_sync(0xffffffffu, idx, off);
            if (ov > v || (ov == v && oi < idx)) { v = ov; idx = oi; }
        }
        if (lane == 0) { s_v[warp] = v; s_i[warp] = idx; }
        __syncthreads();
        if (warp == 0) {
            float v2 = (lane < 16) ? s_v[lane] : -INFINITY;
            int   i2 = (lane < 16) ? s_i[lane] : 0x7fffffff;
#pragma unroll
            for (int off = 16; off; off >>= 1) {
                float ov = __shfl_xor_sync(0xffffffffu, v2, off);
                int   oi = __shfl_xor_sync(0xffffffffu, i2, off);
                if (ov > v2 || (ov == v2 && oi < i2)) { v2 = ov; i2 = oi; }
            }
            if (lane == 0) s_sel = i2;
        }
        __syncthreads();
        const int sel = s_sel;
        if (e == sel) {
            out[(size_t)t * TOPK + it]                             = prob * RSCALE;
            out[(size_t)NUM_TOKENS * TOPK + (size_t)t * TOPK + it] = (float)sel;
            biased = -INFINITY;
        }
    }
}

// ---------------------------------------------------------------------------
extern "C" void kernel_launch(void* const* d_in, const int* in_sizes, int n_in,
                              void* d_out, int out_size) {
    const float* hs   = (const float*)d_in[0];  // hidden_states [8192,4096]
    const float* w    = (const float*)d_in[1];  // classifier_weight [512,4096]
    const float* bias = (const float*)d_in[2];  // e_score_correction_bias [512]
    float* out = (float*)d_out;

    cudaFuncSetAttribute(gemm_tc, cudaFuncAttributeMaxDynamicSharedMemorySize, SMEM_DYN);

    split3_kernel<<<8192, 256>>>(hs, NUM_TOKENS * HIDDEN / 4, 0);
    split3_kernel<<<512, 256>>>(w, NEXP * HIDDEN / 4, 1);

    dim3 grid(NEXP / TILE_N, NUM_TOKENS / TILE_M);   // (8, 64)
    gemm_tc<<<grid, 256, SMEM_DYN>>>();

    softmax_topk<<<NUM_TOKENS, 512>>>(bias, out);
}

// round 10
// speedup vs baseline: 9.2938x; 1.9000x over previous
#include <cuda_runtime.h>
#include <cuda_fp16.h>
#include <math.h>
#include <stdint.h>

#define NUM_TOKENS 8192
#define HIDDEN     4096
#define NEXP       512
#define TOPK       12
#define RSCALE     2.5f

#define TILE_M 128
#define TILE_N 64
#define BK     64
#define NCHUNK (HIDDEN / BK)      // 64
#define RESID_SCALE 2048.0f       // 2^11
#define RESID_INV   (1.0f / 2048.0f)

// device-global scratch (allocation-free per harness rules)
__device__ float g_logits[(size_t)NUM_TOKENS * NEXP];
__device__ __half gA0[(size_t)NUM_TOKENS * HIDDEN];
__device__ __half gA1[(size_t)NUM_TOKENS * HIDDEN];
__device__ __half gB0[(size_t)NEXP * HIDDEN];
__device__ __half gB1[(size_t)NEXP * HIDDEN];

// ---------------------------------------------------------------------------
// helpers (base-ISA: ldmatrix + mma.sync + cp.async)
// ---------------------------------------------------------------------------
__device__ __forceinline__ uint32_t smem_u32(const void* p) {
    uint32_t a;
    asm("{ .reg .u64 t; cvta.to.shared.u64 t, %1; cvt.u32.u64 %0, t; }" : "=r"(a) : "l"(p));
    return a;
}
#define SWZ(off) ((off) ^ (((off) >> 3) & 0x70))

__device__ __forceinline__ void cp16(uint32_t dst, const void* src) {
    asm volatile("cp.async.cg.shared.global [%0], [%1], 16;" :: "r"(dst), "l"(src) : "memory");
}
__device__ __forceinline__ void ldsm4(uint32_t* r, uint32_t addr) {
    asm volatile("ldmatrix.sync.aligned.m8n8.x4.shared.b16 {%0,%1,%2,%3}, [%4];"
                 : "=r"(r[0]), "=r"(r[1]), "=r"(r[2]), "=r"(r[3]) : "r"(addr));
}
__device__ __forceinline__ void mma_f16(float* c, const uint32_t* a, const uint32_t* b) {
    asm volatile(
        "mma.sync.aligned.m16n8k16.row.col.f32.f16.f16.f32 "
        "{%0,%1,%2,%3}, {%4,%5,%6,%7}, {%8,%9}, {%0,%1,%2,%3};"
        : "+f"(c[0]), "+f"(c[1]), "+f"(c[2]), "+f"(c[3])
        : "r"(a[0]), "r"(a[1]), "r"(a[2]), "r"(a[3]), "r"(b[0]), "r"(b[1]));
}

// ---------------------------------------------------------------------------
// Kernel 0: 2-way fp16 split (a = a0 + a1 * 2^-11; a1 stored pre-scaled by 2^11)
// ---------------------------------------------------------------------------
__device__ __forceinline__ void split1(float x, uint16_t& h0, uint16_t& h1) {
    __half a0 = __float2half_rn(x);
    float r = x - __half2float(a0);
    __half a1 = __float2half_rn(r * RESID_SCALE);
    h0 = __half_as_ushort(a0);
    h1 = __half_as_ushort(a1);
}
__global__ void split2_kernel(const float* __restrict__ src, int n4, int which) {
    __half *d0 = which ? gB0 : gA0;
    __half *d1 = which ? gB1 : gA1;
    for (int i = blockIdx.x * blockDim.x + threadIdx.x; i < n4; i += gridDim.x * blockDim.x) {
        float4 v = ((const float4*)src)[i];
        uint16_t a0[4], a1[4];
        split1(v.x, a0[0], a1[0]);
        split1(v.y, a0[1], a1[1]);
        split1(v.z, a0[2], a1[2]);
        split1(v.w, a0[3], a1[3]);
        uint2 p0 = make_uint2((uint32_t)a0[0] | ((uint32_t)a0[1] << 16),
                              (uint32_t)a0[2] | ((uint32_t)a0[3] << 16));
        uint2 p1 = make_uint2((uint32_t)a1[0] | ((uint32_t)a1[1] << 16),
                              (uint32_t)a1[2] | ((uint32_t)a1[3] << 16));
        ((uint2*)d0)[i] = p0;
        ((uint2*)d1)[i] = p1;
    }
}

// ---------------------------------------------------------------------------
// Kernel 1: HMMA emulated-fp32 GEMM  (logits = A @ B^T), 3 MMA streams
// SMEM stage (48 KB): A0 (16K) | A1 (16K) | B0 (8K) | B1 (8K), SW128 rows
// 4-stage cp.async pipeline.
// ---------------------------------------------------------------------------
#define STAGE_BYTES 49152
#define NSTAGE      4
#define SMEM_DYN    (NSTAGE * STAGE_BYTES)

__device__ __forceinline__ void load_chunk(uint32_t sbase, int stage, int c,
                                           int m0, int n0, int tid) {
    const int k0 = c * BK;
    const uint32_t st = sbase + stage * STAGE_BYTES;
#pragma unroll
    for (int i = 0; i < 8; i++) {           // A: 2 splits x 128 rows x 8 segs = 2048
        int o = tid + 256 * i;
        int split = o >> 10;
        int rem = o & 1023;
        int row = rem >> 3, seg = rem & 7;
        const __half* src = split ? gA1 : gA0;
        const __half* g = src + (size_t)(m0 + row) * HIDDEN + k0 + seg * 8;
        uint32_t off = row * 128 + seg * 16;
        cp16(st + split * 16384 + SWZ(off), g);
    }
#pragma unroll
    for (int i = 0; i < 4; i++) {           // B: 2 splits x 64 rows x 8 segs = 1024
        int o = tid + 256 * i;
        int split = o >> 9;
        int rem = o & 511;
        int row = rem >> 3, seg = rem & 7;
        const __half* src = split ? gB1 : gB0;
        const __half* g = src + (size_t)(n0 + row) * HIDDEN + k0 + seg * 8;
        uint32_t off = row * 128 + seg * 16;
        cp16(st + 32768 + split * 8192 + SWZ(off), g);
    }
    asm volatile("cp.async.commit_group;" ::: "memory");
}

__global__ void __launch_bounds__(256, 1) gemm_tc() {
    extern __shared__ char dsm[];
    const uint32_t sbase = smem_u32(dsm);
    const int tid  = threadIdx.x;
    const int wid  = tid >> 5;
    const int lane = tid & 31;
    const int m0 = blockIdx.y * TILE_M;
    const int n0 = blockIdx.x * TILE_N;
    const int wm = (wid >> 1) * 32;     // warp m-offset (4 rows of warps)
    const int wn = (wid & 1) * 32;      // warp n-offset (2 cols of warps)

    float accM[32], accS[32], carry[32];
#pragma unroll
    for (int i = 0; i < 32; i++) { accM[i] = 0.f; accS[i] = 0.f; carry[i] = 0.f; }

    const int arow = wm + (lane & 15);
    const int aseg16 = (lane >> 4) * 16;
    const int brow = wn + ((lane >> 4) << 3) + (lane & 7);
    const int bseg16 = ((lane >> 3) & 1) * 16;

    load_chunk(sbase, 0, 0, m0, n0, tid);
    load_chunk(sbase, 1, 1, m0, n0, tid);
    load_chunk(sbase, 2, 2, m0, n0, tid);

    for (int c = 0; c < NCHUNK; c++) {
        // wait until chunk c is resident (pending groups after wait <= remaining)
        if (c <= NCHUNK - 3)      asm volatile("cp.async.wait_group 2;" ::: "memory");
        else if (c == NCHUNK - 2) asm volatile("cp.async.wait_group 1;" ::: "memory");
        else                      asm volatile("cp.async.wait_group 0;" ::: "memory");
        __syncthreads();   // chunk c visible to all; all warps done with chunk c-1

        if (c + 3 < NCHUNK)
            load_chunk(sbase, (c + 3) & 3, c + 3, m0, n0, tid);  // overwrites slot of c-1

        const uint32_t st = sbase + (c & 3) * STAGE_BYTES;
#pragma unroll
        for (int ks = 0; ks < 4; ks++) {
            uint32_t a0f[2][4], a1f[2][4];
            uint32_t b0f[2][4], b1f[2][4];
#pragma unroll
            for (int mt = 0; mt < 2; mt++) {
                int row = arow + mt * 16;
                uint32_t ad = st + row * 128 + ((ks * 32 + aseg16) ^ ((row & 7) << 4));
                ldsm4(a0f[mt], ad);
                ldsm4(a1f[mt], ad + 16384);
            }
#pragma unroll
            for (int h = 0; h < 2; h++) {
                int row = brow + h * 16;
                uint32_t bd = st + 32768 + row * 128 + ((ks * 32 + bseg16) ^ ((row & 7) << 4));
                ldsm4(b0f[h], bd);
                ldsm4(b1f[h], bd + 8192);
            }
#pragma unroll
            for (int mt = 0; mt < 2; mt++) {
#pragma unroll
                for (int nt = 0; nt < 4; nt++) {
                    float* cM = accM + (mt * 4 + nt) * 4;
                    float* cS = accS + (mt * 4 + nt) * 4;
                    const uint32_t* B0 = &b0f[nt >> 1][(nt & 1) * 2];
                    const uint32_t* B1 = &b1f[nt >> 1][(nt & 1) * 2];
                    mma_f16(cM, a0f[mt], B0);      // main hi*hi
                    mma_f16(cS, a0f[mt], B1);      // cross terms (x 2^11)
                    mma_f16(cS, a1f[mt], B0);
                }
            }
        }

        // split-K flush: every 4 chunks roll main accum into carry (accuracy)
        if ((c & 3) == 3) {
#pragma unroll
            for (int i = 0; i < 32; i++) { carry[i] += accM[i]; accM[i] = 0.f; }
        }
    }

    // writeback: logit = carry(main) + accS * 2^-11
#pragma unroll
    for (int mt = 0; mt < 2; mt++) {
#pragma unroll
        for (int nt = 0; nt < 4; nt++) {
            const float* cM = carry + (mt * 4 + nt) * 4;
            const float* cS = accS + (mt * 4 + nt) * 4;
            int r0  = m0 + wm + mt * 16 + (lane >> 2);
            int col = n0 + wn + nt * 8 + (lane & 3) * 2;
            float2 v0 = make_float2(cM[0] + cS[0] * RESID_INV, cM[1] + cS[1] * RESID_INV);
            float2 v1 = make_float2(cM[2] + cS[2] * RESID_INV, cM[3] + cS[3] * RESID_INV);
            *(float2*)&g_logits[(size_t)r0 * NEXP + col]       = v0;
            *(float2*)&g_logits[(size_t)(r0 + 8) * NEXP + col] = v1;
        }
    }
}

// ---------------------------------------------------------------------------
// Kernel 2: warp-per-token softmax + biased top-12 (ties -> lowest index).
// Each lane holds 16 experts: e = 128*j2 + 4*lane + q  (j = 4*j2 + q).
// No __syncthreads, no smem. out: [weights T*K] then [indices-as-float T*K]
// ---------------------------------------------------------------------------
__global__ void __launch_bounds__(256) softmax_topk(const float* __restrict__ bias,
                                                    float* __restrict__ out) {
    const int warp = threadIdx.x >> 5;
    const int lane = threadIdx.x & 31;
    const int t = blockIdx.x * 8 + warp;

    const float* row = g_logits + (size_t)t * NEXP;
    float p[16], bi[16];
#pragma unroll
    for (int j2 = 0; j2 < 4; j2++) {
        float4 v = ((const float4*)(row + 128 * j2))[lane];
        p[4 * j2 + 0] = v.x; p[4 * j2 + 1] = v.y;
        p[4 * j2 + 2] = v.z; p[4 * j2 + 3] = v.w;
    }

    // max
    float m = p[0];
#pragma unroll
    for (int j = 1; j < 16; j++) m = fmaxf(m, p[j]);
#pragma unroll
    for (int off = 16; off; off >>= 1)
        m = fmaxf(m, __shfl_xor_sync(0xffffffffu, m, off));

    // exp + sum
    float s = 0.f;
#pragma unroll
    for (int j = 0; j < 16; j++) { p[j] = expf(p[j] - m); s += p[j]; }
#pragma unroll
    for (int off = 16; off; off >>= 1)
        s += __shfl_xor_sync(0xffffffffu, s, off);
    const float inv = 1.0f / s;

    // probs + biased scores
#pragma unroll
    for (int j2 = 0; j2 < 4; j2++) {
        float4 b4 = ((const float4*)bias)[32 * j2 + lane];
        p[4 * j2 + 0] *= inv; bi[4 * j2 + 0] = p[4 * j2 + 0] + b4.x;
        p[4 * j2 + 1] *= inv; bi[4 * j2 + 1] = p[4 * j2 + 1] + b4.y;
        p[4 * j2 + 2] *= inv; bi[4 * j2 + 2] = p[4 * j2 + 2] + b4.z;
        p[4 * j2 + 3] *= inv; bi[4 * j2 + 3] = p[4 * j2 + 3] + b4.w;
    }

    // local argmax (scan ascending j => ascending expert idx => lowest-idx ties)
    float lm = -INFINITY; int lj = 0;
#pragma unroll
    for (int j = 0; j < 16; j++)
        if (bi[j] > lm) { lm = bi[j]; lj = j; }
    int le = 128 * (lj >> 2) + 4 * lane + (lj & 3);

    for (int it = 0; it < TOPK; it++) {
        float wv = lm; int wi = le;
#pragma unroll
        for (int off = 16; off; off >>= 1) {
            float ov = __shfl_xor_sync(0xffffffffu, wv, off);
            int   oi = __shfl_xor_sync(0xffffffffu, wi, off);
            if (ov > wv || (ov == wv && oi < wi)) { wv = ov; wi = oi; }
        }
        if (wi == le) {   // this lane owns the winner (index sets are disjoint)
            out[(size_t)t * TOPK + it]                             = p[lj] * RSCALE;
            out[(size_t)NUM_TOKENS * TOPK + (size_t)t * TOPK + it] = (float)le;
            bi[lj] = -INFINITY;
            lm = -INFINITY; lj = 0;
#pragma unroll
            for (int j = 0; j < 16; j++)
                if (bi[j] > lm) { lm = bi[j]; lj = j; }
            le = 128 * (lj >> 2) + 4 * lane + (lj & 3);
        }
    }
}

// ---------------------------------------------------------------------------
extern "C" void kernel_launch(void* const* d_in, const int* in_sizes, int n_in,
                              void* d_out, int out_size) {
    const float* hs   = (const float*)d_in[0];  // hidden_states [8192,4096]
    const float* w    = (const float*)d_in[1];  // classifier_weight [512,4096]
    const float* bias = (const float*)d_in[2];  // e_score_correction_bias [512]
    float* out = (float*)d_out;

    cudaFuncSetAttribute(gemm_tc, cudaFuncAttributeMaxDynamicSharedMemorySize, SMEM_DYN);

    split2_kernel<<<8192, 256>>>(hs, NUM_TOKENS * HIDDEN / 4, 0);
    split2_kernel<<<512, 256>>>(w, NEXP * HIDDEN / 4, 1);

    dim3 grid(NEXP / TILE_N, NUM_TOKENS / TILE_M);   // (8, 64)
    gemm_tc<<<grid, 256, SMEM_DYN>>>();

    softmax_topk<<<NUM_TOKENS / 8, 256>>>(bias, out);
}